// round 9
// baseline (speedup 1.0000x reference)
#include <cuda_runtime.h>

#define DIN  64
#define DOUT 64
#define HH   32
#define HP   16          // h-pairs
#define BB   2048
#define IQ   16          // Din split factor (fine tasks)
#define IPQ  (DIN / IQ)  // 4 i's per task
#define NTASK (DOUT * IQ * 4)   // 4096 tasks: (o, iq, bq)
#define GRID  444               // 3 CTAs/SM * 148 SMs, all resident

// ---- device scratch ----
// w1p record per (o,i,hp): 64B = {0.5*w_f(h0),0.5*w_f(h1) f=0..6, 0.5*B1(h0),0.5*B1(h1)}
__device__ __align__(16) unsigned long long g_w1p[DOUT * DIN * HP * 8];   // 4 MB
// w2: per (o,i): 16 hp-pairs of W2 = 128B
__device__ __align__(16) unsigned long long g_w2[DOUT * DIN * HP];        // 1 MB
__device__ float g_xT[DIN * BB];
__device__ float g_sumB2[DOUT];
__device__ float g_part[IQ * DOUT * BB];    // [iq][o][b] -> coalesced partial stores
__device__ int   g_task;

// ---- f32x2 helpers ----
__device__ __forceinline__ unsigned long long pack2(float a, float b) {
    unsigned long long v;
    asm("mov.b64 %0, {%1, %2};" : "=l"(v) : "f"(a), "f"(b));
    return v;
}
__device__ __forceinline__ void unpack2(unsigned long long v, float& a, float& b) {
    asm("mov.b64 {%0, %1}, %2;" : "=f"(a), "=f"(b) : "l"(v));
}
__device__ __forceinline__ unsigned long long fma2(unsigned long long a,
                                                   unsigned long long b,
                                                   unsigned long long c) {
    unsigned long long d;
    asm("fma.rn.f32x2 %0, %1, %2, %3;" : "=l"(d) : "l"(a), "l"(b), "l"(c));
    return d;
}
__device__ __forceinline__ float tanh_fast(float x) {
    float y;
    asm("tanh.approx.f32 %0, %1;" : "=f"(y) : "f"(x));
    return y;
}
__device__ __forceinline__ unsigned smem_u32(const void* p) {
    unsigned a;
    asm("{ .reg .u64 t; cvta.to.shared.u64 t, %1; cvt.u32.u64 %0, t; }" : "=r"(a) : "l"(p));
    return a;
}
__device__ __forceinline__ void cp16(unsigned s, const void* g) {
    asm volatile("cp.async.cg.shared.global [%0], [%1], 16;" :: "r"(s), "l"(g));
}

// feats order matches reference: [x, sin(1x), sin(2x), sin(4x), cos(1x), cos(2x), cos(4x)]
__device__ __forceinline__ void make_feats(float x, unsigned long long* fp) {
    float s1 = __sinf(x),  c1 = __cosf(x);
    float x2 = x + x;
    float s2 = __sinf(x2), c2 = __cosf(x2);
    float x4 = x2 + x2;
    float s4 = __sinf(x4), c4 = __cosf(x4);
    fp[0] = pack2(x,  x);
    fp[1] = pack2(s1, s1);
    fp[2] = pack2(s2, s2);
    fp[3] = pack2(s4, s4);
    fp[4] = pack2(c1, c1);
    fp[5] = pack2(c2, c2);
    fp[6] = pack2(c4, c4);
}

// one edge-MLP evaluation for one b (h-pair packed), weights pre-scaled by 0.5
__device__ __forceinline__ void edge_eval(ulonglong2 q0, ulonglong2 q1,
                                          ulonglong2 q2, ulonglong2 q3,
                                          unsigned long long w2p,
                                          const unsigned long long* f,
                                          unsigned long long& acc) {
    unsigned long long u = fma2(q0.x, f[0], q3.y);  // q3.y = 0.5*B1 pair
    u = fma2(q0.y, f[1], u);
    u = fma2(q1.x, f[2], u);
    u = fma2(q1.y, f[3], u);
    u = fma2(q2.x, f[4], u);
    u = fma2(q2.y, f[5], u);
    u = fma2(q3.x, f[6], u);                        // u = h/2
    float a0, a1;
    unpack2(u, a0, a1);
    unsigned long long tp = pack2(tanh_fast(a0), tanh_fast(a1));
    unsigned long long s = fma2(u, tp, u);          // silu(h) = (h/2)(1+tanh(h/2))
    acc = fma2(s, w2p, acc);
}

// ---- prologue 1: tiled x transpose (coalesced both sides) ----
__global__ void prep_x_t(const float* __restrict__ x) {
    __shared__ float tile[32][33];
    int bx = blockIdx.x;             // 64 b-tiles of 32
    int by = blockIdx.y;             // 2 i-tiles of 32
    int tx = threadIdx.x, ty = threadIdx.y;   // 32 x 8
#pragma unroll
    for (int k = 0; k < 4; k++) {
        int b = bx * 32 + ty + k * 8;
        tile[ty + k * 8][tx] = x[b * DIN + by * 32 + tx];
    }
    __syncthreads();
#pragma unroll
    for (int k = 0; k < 4; k++) {
        int i = by * 32 + ty + k * 8;
        g_xT[i * BB + bx * 32 + tx] = tile[tx][ty + k * 8];
    }
}

// ---- prologue 2: weight repack + B2 row-sum + task-counter reset ----
#define NRP (DOUT * DIN * HP)
__global__ void prep_w(const float* __restrict__ W1, const float* __restrict__ W2,
                       const float* __restrict__ B1, const float* __restrict__ B2) {
    if (blockIdx.x == 0 && threadIdx.x == 0) g_task = GRID;
    int t = blockIdx.x * 256 + threadIdx.x;
    if (t < NRP) {
        int hp = t & 15;
        int i  = (t >> 4) & 63;
        int o  = t >> 10;
        int h0 = hp * 2, h1 = h0 + 1;

        const float* w1b = W1 + (((size_t)i * DOUT + o) * HH) * 7;  // W1[i][o][h][f]
        float* dst = ((float*)g_w1p) + (size_t)t * 16;
#pragma unroll
        for (int f = 0; f < 7; f++) {
            dst[2 * f]     = 0.5f * w1b[h0 * 7 + f];
            dst[2 * f + 1] = 0.5f * w1b[h1 * 7 + f];
        }
        const float* b1b = B1 + ((size_t)i * DOUT + o) * HH;
        dst[14] = 0.5f * b1b[h0];
        dst[15] = 0.5f * b1b[h1];

        const float* w2b = W2 + ((size_t)i * DOUT + o) * HH;  // W2[i][o][0][h]
        float* d2 = ((float*)g_w2) + (((size_t)o * DIN + i) * HP + hp) * 2;
        d2[0] = w2b[h0];
        d2[1] = w2b[h1];
        return;
    }
    t -= NRP;
    if (t < DOUT) {
        float s = 0.f;
        for (int i = 0; i < DIN; i++) s += B2[i * DOUT + t];
        g_sumB2[t] = s;
    }
}

// ---- main: persistent CTAs + atomic work-stealing + double-buffered cp.async ----
// task t: bq = t&3 (512 b's), iq = (t>>2)&15 (4 i's), o = t>>6.
// Prefetched per task: 4.5KB weights + 8KB x slice.
struct TaskBuf {
    ulonglong2 w1[IPQ * HP * 4];   // 256 entries, 4 KB
    ulonglong2 w2[IPQ * HP / 2];   // 32 entries, 0.5 KB
    float      x[IPQ * 512];       // 8 KB
};

__device__ __forceinline__ void prefetch_task(TaskBuf* buf, int task, int tid) {
    int bq = task & 3;
    int iq = (task >> 2) & 15;
    int o  = task >> 6;
    int i0 = iq * IPQ;
    const ulonglong2* gw1 = ((const ulonglong2*)g_w1p) + ((size_t)o * DIN + i0) * (HP * 4);
    const ulonglong2* gw2 = ((const ulonglong2*)g_w2)  + ((size_t)o * DIN + i0) * (HP / 2);
    cp16(smem_u32(&buf->w1[tid]), gw1 + tid);                       // 256 entries
    if (tid < IPQ * HP / 2) cp16(smem_u32(&buf->w2[tid]), gw2 + tid);
    const float* gx = g_xT + i0 * BB + bq * 512;
#pragma unroll
    for (int c = tid; c < IPQ * 128; c += 256)                      // 512 x 16B chunks
        cp16(smem_u32(&buf->x[c * 4]), gx + (c >> 7) * BB + (c & 127) * 4);
    asm volatile("cp.async.commit_group;" ::: "memory");
}

__global__ void __launch_bounds__(256, 3) kan_main() {
    __shared__ __align__(16) TaskBuf s_buf[2];   // 25 KB
    __shared__ int s_next;

    int tid  = threadIdx.x;
    int lane = tid & 31;
    int w    = tid >> 5;

    int t = blockIdx.x;
    prefetch_task(&s_buf[0], t, tid);
    int n = 0;

    while (t < NTASK) {
        if (tid == 0) s_next = atomicAdd(&g_task, 1);
        asm volatile("cp.async.wait_group 0;" ::: "memory");
        __syncthreads();                       // buf n ready; prev compute done; s_next visible
        int tn = s_next;
        if (tn < NTASK) prefetch_task(&s_buf[n ^ 1], tn, tid);

        TaskBuf* B = &s_buf[n];
        int bq = t & 3;
        int iq = (t >> 2) & 15;
        int o  = t >> 6;

        unsigned long long accA = 0ull, accB = 0ull;
        unsigned long long fA[7], fB[7];

#pragma unroll 1
        for (int ii = 0; ii < IPQ; ii++) {
            make_feats(B->x[ii * 512 + w * 64 + lane],      fA);
            make_feats(B->x[ii * 512 + w * 64 + lane + 32], fB);

            const ulonglong2* wr  = B->w1 + ii * (HP * 4);
            const ulonglong2* w2r = B->w2 + ii * (HP / 2);

#pragma unroll 2
            for (int hpp = 0; hpp < HP / 2; hpp++) {
                ulonglong2 w2q = w2r[hpp];   // W2 pairs for hp=2hpp (.x), 2hpp+1 (.y)
#pragma unroll
                for (int k = 0; k < 2; k++) {
                    int hp = 2 * hpp + k;
                    ulonglong2 q0 = wr[hp * 4 + 0];
                    ulonglong2 q1 = wr[hp * 4 + 1];
                    ulonglong2 q2 = wr[hp * 4 + 2];
                    ulonglong2 q3 = wr[hp * 4 + 3];
                    unsigned long long w2p = k ? w2q.y : w2q.x;
                    edge_eval(q0, q1, q2, q3, w2p, fA, accA);
                    edge_eval(q0, q1, q2, q3, w2p, fB, accB);
                }
            }
        }

        float r0, r1;
        float* pp = g_part + ((size_t)iq * DOUT + o) * BB + bq * 512 + w * 64 + lane;
        unpack2(accA, r0, r1); pp[0]  = r0 + r1;   // coalesced
        unpack2(accB, r0, r1); pp[32] = r0 + r1;

        t = tn;
        n ^= 1;
    }
}

// ---- epilogue: sum 16 partials + bias; coalesced reads ----
__global__ void epilogue(float* __restrict__ out) {
    int idx = blockIdx.x * 256 + threadIdx.x;    // idx = o*BB + b
    if (idx >= DOUT * BB) return;
    int o = idx >> 11;
    int b = idx & (BB - 1);
    float s = g_sumB2[o];
#pragma unroll
    for (int q = 0; q < IQ; q++) s += g_part[(size_t)q * DOUT * BB + idx];
    out[b * DOUT + o] = s;
}

extern "C" void kernel_launch(void* const* d_in, const int* in_sizes, int n_in,
                              void* d_out, int out_size) {
    const float* x  = (const float*)d_in[0];
    const float* W1 = (const float*)d_in[1];
    const float* W2 = (const float*)d_in[2];
    const float* B1 = (const float*)d_in[3];
    const float* B2 = (const float*)d_in[4];
    (void)in_sizes; (void)n_in; (void)out_size;

    dim3 tb(32, 8);
    dim3 tg(64, 2);
    prep_x_t<<<tg, tb>>>(x);
    prep_w<<<(NRP + DOUT + 255) / 256, 256>>>(W1, W2, B1, B2);
    kan_main<<<GRID, 256>>>();
    epilogue<<<(DOUT * BB + 255) / 256, 256>>>((float*)d_out);
}

// round 10
// speedup vs baseline: 1.1516x; 1.1516x over previous
#include <cuda_runtime.h>

#define DIN  64
#define DOUT 64
#define HH   32
#define HP   16          // h-pairs
#define BB   2048
#define IQ   8           // Din split factor
#define IPQ  (DIN / IQ)  // 8 i's per CTA

// ---- device scratch ----
// w1p record per (o,i,hp): 64B = {0.5*w_f(h0),0.5*w_f(h1) f=0..6, 0.5*B1(h0),0.5*B1(h1)}
__device__ __align__(16) unsigned long long g_w1p[DOUT * DIN * HP * 8];   // 4 MB
// w2: per (o,i): 16 hp-pairs of W2 = 128B
__device__ __align__(16) unsigned long long g_w2[DOUT * DIN * HP];        // 1 MB
__device__ float g_xT[DIN * BB];
__device__ float g_sumB2[DOUT];
__device__ float g_part[IQ * DOUT * BB];    // [iq][o][b] -> coalesced stores+reads, 4 MB

// ---- f32x2 helpers ----
__device__ __forceinline__ unsigned long long pack2(float a, float b) {
    unsigned long long v;
    asm("mov.b64 %0, {%1, %2};" : "=l"(v) : "f"(a), "f"(b));
    return v;
}
__device__ __forceinline__ void unpack2(unsigned long long v, float& a, float& b) {
    asm("mov.b64 {%0, %1}, %2;" : "=f"(a), "=f"(b) : "l"(v));
}
__device__ __forceinline__ unsigned long long fma2(unsigned long long a,
                                                   unsigned long long b,
                                                   unsigned long long c) {
    unsigned long long d;
    asm("fma.rn.f32x2 %0, %1, %2, %3;" : "=l"(d) : "l"(a), "l"(b), "l"(c));
    return d;
}
__device__ __forceinline__ float tanh_fast(float x) {
    float y;
    asm("tanh.approx.f32 %0, %1;" : "=f"(y) : "f"(x));
    return y;
}

// feats order matches reference: [x, sin(1x), sin(2x), sin(4x), cos(1x), cos(2x), cos(4x)]
__device__ __forceinline__ void make_feats(float x, unsigned long long* fp) {
    float s1 = __sinf(x),  c1 = __cosf(x);
    float x2 = x + x;
    float s2 = __sinf(x2), c2 = __cosf(x2);
    float x4 = x2 + x2;
    float s4 = __sinf(x4), c4 = __cosf(x4);
    fp[0] = pack2(x,  x);
    fp[1] = pack2(s1, s1);
    fp[2] = pack2(s2, s2);
    fp[3] = pack2(s4, s4);
    fp[4] = pack2(c1, c1);
    fp[5] = pack2(c2, c2);
    fp[6] = pack2(c4, c4);
}

// one edge-MLP evaluation for one b (h-pair packed), weights pre-scaled by 0.5
__device__ __forceinline__ void edge_eval(ulonglong2 q0, ulonglong2 q1,
                                          ulonglong2 q2, ulonglong2 q3,
                                          unsigned long long w2p,
                                          const unsigned long long* f,
                                          unsigned long long& acc) {
    unsigned long long u = fma2(q0.x, f[0], q3.y);  // q3.y = 0.5*B1 pair
    u = fma2(q0.y, f[1], u);
    u = fma2(q1.x, f[2], u);
    u = fma2(q1.y, f[3], u);
    u = fma2(q2.x, f[4], u);
    u = fma2(q2.y, f[5], u);
    u = fma2(q3.x, f[6], u);                        // u = h/2
    float a0, a1;
    unpack2(u, a0, a1);
    unsigned long long tp = pack2(tanh_fast(a0), tanh_fast(a1));
    unsigned long long s = fma2(u, tp, u);          // silu(h) = (h/2)(1+tanh(h/2))
    acc = fma2(s, w2p, acc);
}

// ---- prologue 1: tiled x transpose (coalesced both sides) ----
__global__ void prep_x_t(const float* __restrict__ x) {
    __shared__ float tile[32][33];
    int bx = blockIdx.x;             // 64 b-tiles of 32
    int by = blockIdx.y;             // 2 i-tiles of 32
    int tx = threadIdx.x, ty = threadIdx.y;   // 32 x 8
#pragma unroll
    for (int k = 0; k < 4; k++) {
        int b = bx * 32 + ty + k * 8;
        tile[ty + k * 8][tx] = x[b * DIN + by * 32 + tx];
    }
    __syncthreads();
#pragma unroll
    for (int k = 0; k < 4; k++) {
        int i = by * 32 + ty + k * 8;
        g_xT[i * BB + bx * 32 + tx] = tile[tx][ty + k * 8];
    }
}

// ---- prologue 2: weight repack + B2 row-sum ----
#define NRP (DOUT * DIN * HP)
__global__ void prep_w(const float* __restrict__ W1, const float* __restrict__ W2,
                       const float* __restrict__ B1, const float* __restrict__ B2) {
    int t = blockIdx.x * 256 + threadIdx.x;
    if (t < NRP) {
        int hp = t & 15;
        int i  = (t >> 4) & 63;
        int o  = t >> 10;
        int h0 = hp * 2, h1 = h0 + 1;

        const float* w1b = W1 + (((size_t)i * DOUT + o) * HH) * 7;  // W1[i][o][h][f]
        float* dst = ((float*)g_w1p) + (size_t)t * 16;
#pragma unroll
        for (int f = 0; f < 7; f++) {
            dst[2 * f]     = 0.5f * w1b[h0 * 7 + f];
            dst[2 * f + 1] = 0.5f * w1b[h1 * 7 + f];
        }
        const float* b1b = B1 + ((size_t)i * DOUT + o) * HH;
        dst[14] = 0.5f * b1b[h0];
        dst[15] = 0.5f * b1b[h1];

        const float* w2b = W2 + ((size_t)i * DOUT + o) * HH;  // W2[i][o][0][h]
        float* d2 = ((float*)g_w2) + (((size_t)o * DIN + i) * HP + hp) * 2;
        d2[0] = w2b[h0];
        d2[1] = w2b[h1];
        return;
    }
    t -= NRP;
    if (t < DOUT) {
        float s = 0.f;
        for (int i = 0; i < DIN; i++) s += B2[i * DOUT + t];
        g_sumB2[t] = s;
    }
}

// ---- main fused kernel ----
// CTA = 8 warps, one (o, iq, bq): 8 i's, 512 b's. 9KB weight slice in smem.
// Lane owns 2 b's. 3 CTAs/SM. grid = 64 o * 8 iq * 4 bq = 2048 CTAs
// -> 4.61 waves over 444 slots (vs 2.31 at IQ=4): tail loss 23% -> 8%.
__global__ void __launch_bounds__(256, 3) kan_main() {
    __shared__ __align__(16) ulonglong2 s_w1[IPQ * HP * 4];   // 512 entries, 8 KB
    __shared__ __align__(16) ulonglong2 s_w2[IPQ * HP / 2];   // 64 entries, 1 KB

    int lane = threadIdx.x & 31;
    int w    = threadIdx.x >> 5;
    int o    = blockIdx.x & 63;
    int iq   = (blockIdx.x >> 6) & 7;
    int bq   = blockIdx.x >> 9;             // 0..3
    int b0   = bq * 512 + w * 64 + lane;
    int i0   = iq * IPQ;

    // cooperative weight-slice load (coalesced LDG.128 -> STS.128)
    {
        const ulonglong2* gw1 = ((const ulonglong2*)g_w1p) + ((size_t)o * DIN + i0) * (HP * 4);
        const ulonglong2* gw2 = ((const ulonglong2*)g_w2)  + ((size_t)o * DIN + i0) * (HP / 2);
#pragma unroll
        for (int t = threadIdx.x; t < IPQ * HP * 4; t += 256) s_w1[t] = gw1[t];
        if (threadIdx.x < IPQ * HP / 2) s_w2[threadIdx.x] = gw2[threadIdx.x];
    }
    __syncthreads();

    unsigned long long accA = 0ull, accB = 0ull;
    unsigned long long fA[7], fB[7];

    const float* xr = g_xT + i0 * BB + b0;
    float nxa = xr[0], nxb = xr[32];

#pragma unroll 1
    for (int ii = 0; ii < IPQ; ii++) {
        float xa = nxa, xb = nxb;
        if (ii + 1 < IPQ) {                      // prefetch next i's x
            nxa = xr[(ii + 1) * BB];
            nxb = xr[(ii + 1) * BB + 32];
        }
        make_feats(xa, fA);
        make_feats(xb, fB);

        const ulonglong2* wr  = s_w1 + ii * (HP * 4);
        const ulonglong2* w2r = s_w2 + ii * (HP / 2);

#pragma unroll 2
        for (int hpp = 0; hpp < HP / 2; hpp++) {
            ulonglong2 w2q = w2r[hpp];      // W2 pairs for hp=2hpp (.x), 2hpp+1 (.y)
#pragma unroll
            for (int k = 0; k < 2; k++) {
                int hp = 2 * hpp + k;
                ulonglong2 q0 = wr[hp * 4 + 0];
                ulonglong2 q1 = wr[hp * 4 + 1];
                ulonglong2 q2 = wr[hp * 4 + 2];
                ulonglong2 q3 = wr[hp * 4 + 3];
                unsigned long long w2p = k ? w2q.y : w2q.x;
                edge_eval(q0, q1, q2, q3, w2p, fA, accA);
                edge_eval(q0, q1, q2, q3, w2p, fB, accB);
            }
        }
    }

    float r0, r1;
    float* pp = g_part + ((size_t)iq * DOUT + o) * BB + b0;
    unpack2(accA, r0, r1); pp[0]  = r0 + r1;    // coalesced
    unpack2(accB, r0, r1); pp[32] = r0 + r1;
}

// ---- epilogue: sum 8 partials (coalesced) + bias ----
__global__ void epilogue(float* __restrict__ out) {
    int idx = blockIdx.x * 256 + threadIdx.x;    // idx = o*BB + b
    if (idx >= DOUT * BB) return;
    int o = idx >> 11;
    int b = idx & (BB - 1);
    float s = g_sumB2[o];
#pragma unroll
    for (int q = 0; q < IQ; q++) s += g_part[(size_t)q * DOUT * BB + idx];
    out[b * DOUT + o] = s;
}

extern "C" void kernel_launch(void* const* d_in, const int* in_sizes, int n_in,
                              void* d_out, int out_size) {
    const float* x  = (const float*)d_in[0];
    const float* W1 = (const float*)d_in[1];
    const float* W2 = (const float*)d_in[2];
    const float* B1 = (const float*)d_in[3];
    const float* B2 = (const float*)d_in[4];
    (void)in_sizes; (void)n_in; (void)out_size;

    dim3 tb(32, 8);
    dim3 tg(64, 2);
    prep_x_t<<<tg, tb>>>(x);
    prep_w<<<(NRP + DOUT + 255) / 256, 256>>>(W1, W2, B1, B2);
    kan_main<<<2048, 256>>>();
    epilogue<<<(DOUT * BB + 255) / 256, 256>>>((float*)d_out);
}